// round 1
// baseline (speedup 1.0000x reference)
#include <cuda_runtime.h>

#define T_SEQ 2048
#define NB    4
#define NHEAD 16
#define DK    64
#define DMODEL 1024
#define HDIM  1024   // NHEAD*DK

// Scratch (allocation-free rule: __device__ globals)
__device__ float g_Q[NB * NHEAD * T_SEQ * DK];   // 32 MB, [n,h,t,d]
__device__ float g_V[NB * NHEAD * T_SEQ * DK];   // 32 MB, [n,h,t,d]
__device__ float g_A[NB * T_SEQ * HDIM];         // 32 MB, [n,t,h*d] merged

// ---------------------------------------------------------------------------
// SGEMM with bias: C = X[M,K] @ W[K,N] + b[N]
// headsplit=1: scatter output to [n, h, t, d] layout (for Q/V projections)
// headsplit=0: plain row-major [M, N]
// Tiles: 128x128x16, 256 threads, 8x8 frag per thread.
// ---------------------------------------------------------------------------
__global__ __launch_bounds__(256)
void sgemm_bias(const float* __restrict__ X, const float* __restrict__ W,
                const float* __restrict__ bias, float* __restrict__ C,
                int headsplit)
{
    const int K = DMODEL;
    const int N = HDIM;

    __shared__ float As[16][132];   // transposed A tile, padded (stride 132 keeps float4 align)
    __shared__ float Bs[16][128];

    const int tid = threadIdx.x;
    const int tx = tid & 15;
    const int ty = tid >> 4;
    const int bm = blockIdx.y * 128;
    const int bn = blockIdx.x * 128;

    float acc[8][8];
#pragma unroll
    for (int i = 0; i < 8; i++)
#pragma unroll
        for (int j = 0; j < 8; j++) acc[i][j] = 0.f;

    const int arow = tid >> 2;        // 0..63
    const int acol = (tid & 3) * 4;   // 0,4,8,12
    const int brow = tid >> 5;        // 0..7
    const int bcol = (tid & 31) * 4;

    for (int k0 = 0; k0 < K; k0 += 16) {
#pragma unroll
        for (int it = 0; it < 2; it++) {
            float4 a = *(const float4*)&X[(size_t)(bm + arow + it * 64) * K + k0 + acol];
            As[acol + 0][arow + it * 64] = a.x;
            As[acol + 1][arow + it * 64] = a.y;
            As[acol + 2][arow + it * 64] = a.z;
            As[acol + 3][arow + it * 64] = a.w;
        }
#pragma unroll
        for (int it = 0; it < 2; it++) {
            float4 b = *(const float4*)&W[(size_t)(k0 + brow + it * 8) * N + bn + bcol];
            *(float4*)&Bs[brow + it * 8][bcol] = b;
        }
        __syncthreads();

#pragma unroll
        for (int k = 0; k < 16; k++) {
            float a[8], b[8];
            *(float4*)&a[0] = *(const float4*)&As[k][ty * 4];
            *(float4*)&a[4] = *(const float4*)&As[k][64 + ty * 4];
            *(float4*)&b[0] = *(const float4*)&Bs[k][tx * 4];
            *(float4*)&b[4] = *(const float4*)&Bs[k][64 + tx * 4];
#pragma unroll
            for (int i = 0; i < 8; i++)
#pragma unroll
                for (int j = 0; j < 8; j++)
                    acc[i][j] += a[i] * b[j];
        }
        __syncthreads();
    }

    // epilogue
#pragma unroll
    for (int i = 0; i < 8; i++) {
        const int rloc = (i < 4) ? (ty * 4 + i) : (64 + ty * 4 + i - 4);
        const int row = bm + rloc;
#pragma unroll
        for (int jg = 0; jg < 2; jg++) {
            const int col = bn + jg * 64 + tx * 4;
            float4 r;
            r.x = acc[i][jg * 4 + 0] + bias[col + 0];
            r.y = acc[i][jg * 4 + 1] + bias[col + 1];
            r.z = acc[i][jg * 4 + 2] + bias[col + 2];
            r.w = acc[i][jg * 4 + 3] + bias[col + 3];
            if (!headsplit) {
                *(float4*)&C[(size_t)row * N + col] = r;
            } else {
                const int n = row >> 11;        // /2048
                const int t = row & 2047;
                const int h = col >> 6;
                const int d = col & 63;
                *(float4*)&C[(size_t)(((n * NHEAD + h) * T_SEQ) + t) * DK + d] = r;
            }
        }
    }
}

// ---------------------------------------------------------------------------
// Flash-style attention: per (n,h), S = Q·V^T / 8, mask, online softmax,
// O = softmax(S) · V. BM=128 queries/block, BN=64 keys/iter, 256 threads.
// Output written in merged [n, t, h*64+d] layout for the final GEMM.
// Dynamic smem: Qs 32KB + Vs 16KB + Ps 32KB = 80KB.
// ---------------------------------------------------------------------------
#define ATTN_SMEM_BYTES ((128 * 64 + 64 * 64 + 128 * 64) * 4)

__global__ __launch_bounds__(256)
void attn_kernel(const float* __restrict__ Q, const float* __restrict__ V,
                 const int* __restrict__ mask, float* __restrict__ A)
{
    extern __shared__ float smem[];
    float* Qs = smem;                 // [128][64]
    float* Vs = smem + 128 * 64;      // [64][64]
    float* Ps = Vs + 64 * 64;         // [128][64]

    const int tid = threadIdx.x;
    const int tx = tid & 15;
    const int ty = tid >> 4;
    const int nh = blockIdx.y;
    const int n = nh / NHEAD;
    const int h = nh % NHEAD;
    const int q0 = blockIdx.x * 128;

    const float* Qh = Q + (size_t)nh * T_SEQ * DK + (size_t)q0 * DK;
    const float* Vh = V + (size_t)nh * T_SEQ * DK;
    const int* mrow = mask + n * T_SEQ;

    // load Q tile (128x64 = 2048 float4, 8 per thread)
#pragma unroll
    for (int it = 0; it < 8; it++) {
        int idx = tid + it * 256;
        ((float4*)Qs)[idx] = ((const float4*)Qh)[idx];
    }

    float o[8][4];
    float m_i[8], l_i[8];
#pragma unroll
    for (int r = 0; r < 8; r++) {
        m_i[r] = -1e30f;
        l_i[r] = 0.f;
#pragma unroll
        for (int c = 0; c < 4; c++) o[r][c] = 0.f;
    }

    for (int j0 = 0; j0 < T_SEQ; j0 += 64) {
        __syncthreads();   // previous iter's reads of Vs/Ps done (also covers Qs store->load)
        // load V tile (64x64 = 1024 float4, 4 per thread)
#pragma unroll
        for (int it = 0; it < 4; it++) {
            int idx = tid + it * 256;
            ((float4*)Vs)[idx] = ((const float4*)(Vh + (size_t)j0 * DK))[idx];
        }
        __syncthreads();

        // S = Q V^T ; rows i = ty*8+r, cols j = tx*4+c
        float s[8][4];
#pragma unroll
        for (int r = 0; r < 8; r++)
#pragma unroll
            for (int c = 0; c < 4; c++) s[r][c] = 0.f;

#pragma unroll
        for (int d4 = 0; d4 < 16; d4++) {
            float4 q[8], v[4];
#pragma unroll
            for (int r = 0; r < 8; r++) q[r] = ((const float4*)Qs)[(ty * 8 + r) * 16 + d4];
#pragma unroll
            for (int c = 0; c < 4; c++) v[c] = ((const float4*)Vs)[(tx * 4 + c) * 16 + d4];
#pragma unroll
            for (int r = 0; r < 8; r++)
#pragma unroll
                for (int c = 0; c < 4; c++)
                    s[r][c] += q[r].x * v[c].x + q[r].y * v[c].y +
                               q[r].z * v[c].z + q[r].w * v[c].w;
        }

        // mask + scale (1/sqrt(64) = 0.125)
        int mv[4];
#pragma unroll
        for (int c = 0; c < 4; c++) mv[c] = mrow[j0 + tx * 4 + c];
#pragma unroll
        for (int r = 0; r < 8; r++)
#pragma unroll
            for (int c = 0; c < 4; c++)
                s[r][c] = mv[c] ? s[r][c] * 0.125f : -1e30f;

        // online softmax, row-wise (row group = 16 lanes sharing ty)
#pragma unroll
        for (int r = 0; r < 8; r++) {
            float tmax = fmaxf(fmaxf(s[r][0], s[r][1]), fmaxf(s[r][2], s[r][3]));
#pragma unroll
            for (int off = 8; off >= 1; off >>= 1)
                tmax = fmaxf(tmax, __shfl_xor_sync(0xffffffffu, tmax, off, 16));
            const float mnew = fmaxf(m_i[r], tmax);
            const float scale = __expf(m_i[r] - mnew);
            m_i[r] = mnew;
            float tsum = 0.f;
#pragma unroll
            for (int c = 0; c < 4; c++) {
                const float p = __expf(s[r][c] - mnew);
                s[r][c] = p;
                tsum += p;
            }
#pragma unroll
            for (int off = 8; off >= 1; off >>= 1)
                tsum += __shfl_xor_sync(0xffffffffu, tsum, off, 16);
            l_i[r] = l_i[r] * scale + tsum;
#pragma unroll
            for (int c = 0; c < 4; c++) o[r][c] *= scale;
            *(float4*)&Ps[(ty * 8 + r) * 64 + tx * 4] =
                make_float4(s[r][0], s[r][1], s[r][2], s[r][3]);
        }
        __syncthreads();

        // O += P @ V ; cols d = tx*4+c
#pragma unroll
        for (int j4 = 0; j4 < 16; j4++) {
            float4 p[8], v[4];
#pragma unroll
            for (int r = 0; r < 8; r++) p[r] = ((const float4*)Ps)[(ty * 8 + r) * 16 + j4];
#pragma unroll
            for (int jj = 0; jj < 4; jj++) v[jj] = ((const float4*)Vs)[(j4 * 4 + jj) * 16 + tx];
#pragma unroll
            for (int r = 0; r < 8; r++) {
                o[r][0] += p[r].x * v[0].x + p[r].y * v[1].x + p[r].z * v[2].x + p[r].w * v[3].x;
                o[r][1] += p[r].x * v[0].y + p[r].y * v[1].y + p[r].z * v[2].y + p[r].w * v[3].y;
                o[r][2] += p[r].x * v[0].z + p[r].y * v[1].z + p[r].z * v[2].z + p[r].w * v[3].z;
                o[r][3] += p[r].x * v[0].w + p[r].y * v[1].w + p[r].z * v[2].w + p[r].w * v[3].w;
            }
        }
    }

    // epilogue: divide by l, write merged [n, t, h*64+d]
#pragma unroll
    for (int r = 0; r < 8; r++) {
        const int trow = q0 + ty * 8 + r;
        const float inv = 1.f / l_i[r];
        float4 rv = make_float4(o[r][0] * inv, o[r][1] * inv, o[r][2] * inv, o[r][3] * inv);
        *(float4*)&A[(size_t)((n * T_SEQ + trow) * NHEAD + h) * DK + tx * 4] = rv;
    }
}

// ---------------------------------------------------------------------------
// Launch: skip K projection entirely (reference never uses k in scores/output).
// Inputs (metadata order): 0 x_k, 1 x_v, 2 x_q, 3 mask, 4 Wk, 5 bk,
//                          6 Wv, 7 bv, 8 Wq, 9 bq, 10 Wf, 11 bf
// ---------------------------------------------------------------------------
extern "C" void kernel_launch(void* const* d_in, const int* in_sizes, int n_in,
                              void* d_out, int out_size)
{
    const float* x_v  = (const float*)d_in[1];
    const float* x_q  = (const float*)d_in[2];
    const int*   mask = (const int*)d_in[3];
    const float* Wv   = (const float*)d_in[6];
    const float* bv   = (const float*)d_in[7];
    const float* Wq   = (const float*)d_in[8];
    const float* bq   = (const float*)d_in[9];
    const float* Wf   = (const float*)d_in[10];
    const float* bf   = (const float*)d_in[11];
    float* out = (float*)d_out;

    float *gQ, *gV, *gA;
    cudaGetSymbolAddress((void**)&gQ, g_Q);
    cudaGetSymbolAddress((void**)&gV, g_V);
    cudaGetSymbolAddress((void**)&gA, g_A);

    cudaFuncSetAttribute(attn_kernel, cudaFuncAttributeMaxDynamicSharedMemorySize,
                         ATTN_SMEM_BYTES);

    dim3 gg(HDIM / 128, (NB * T_SEQ) / 128);
    sgemm_bias<<<gg, 256>>>(x_q, Wq, bq, gQ, 1);
    sgemm_bias<<<gg, 256>>>(x_v, Wv, bv, gV, 1);
    attn_kernel<<<dim3(T_SEQ / 128, NB * NHEAD), 256, ATTN_SMEM_BYTES>>>(gQ, gV, mask, gA);
    sgemm_bias<<<gg, 256>>>(gA, Wf, bf, out, 0);
}

// round 2
// speedup vs baseline: 3.8938x; 3.8938x over previous
#include <cuda_runtime.h>
#include <cstdint>

#define T_SEQ 2048
#define NB    4
#define NHEAD 16
#define DK    64
#define DMODEL 1024
#define HDIM  1024

// Scratch (allocation-free rule: __device__ globals)
__device__ float g_Q[NB * NHEAD * T_SEQ * DK];   // [n,h,t,d]
__device__ float g_V[NB * NHEAD * T_SEQ * DK];   // [n,h,t,d]
__device__ float g_A[NB * T_SEQ * HDIM];         // [n,t,h*d]

// ---------------------------------------------------------------------------
// tf32 helpers
// ---------------------------------------------------------------------------
__device__ __forceinline__ uint32_t f2tf(float f) {
    uint32_t r;
    asm("cvt.rna.tf32.f32 %0, %1;" : "=r"(r) : "f"(f));
    return r;
}

__device__ __forceinline__ void mma8(float* c, const uint32_t* a, uint32_t b0, uint32_t b1) {
    asm volatile(
        "mma.sync.aligned.m16n8k8.row.col.f32.tf32.tf32.f32 "
        "{%0,%1,%2,%3}, {%4,%5,%6,%7}, {%8,%9}, {%0,%1,%2,%3};"
        : "+f"(c[0]), "+f"(c[1]), "+f"(c[2]), "+f"(c[3])
        : "r"(a[0]), "r"(a[1]), "r"(a[2]), "r"(a[3]), "r"(b0), "r"(b1));
}

// ---------------------------------------------------------------------------
// tf32 GEMM with bias: C = X[M,1024] @ W[1024,1024] + b
// Block 128x128, K-step 32. 8 warps: wm=warp&3 (32 rows), wn=warp>>2 (64 cols).
// headsplit=1 scatters into [n,h,t,d].
// ---------------------------------------------------------------------------
#define GLDA 36
#define GLDB 132

__global__ __launch_bounds__(256)
void gemm_tf32(const float* __restrict__ X, const float* __restrict__ W,
               const float* __restrict__ bias, float* __restrict__ C, int headsplit)
{
    __shared__ uint32_t As[128 * GLDA];   // [m][k]
    __shared__ uint32_t Bs[32 * GLDB];    // [k][n]

    const int tid = threadIdx.x;
    const int lane = tid & 31;
    const int warp = tid >> 5;
    const int g = lane >> 2;      // 0..7
    const int t = lane & 3;       // 0..3
    const int wm = warp & 3;
    const int wn = warp >> 2;
    const int bm = blockIdx.y * 128;
    const int bn = blockIdx.x * 128;

    float c[2][8][4];
#pragma unroll
    for (int mt = 0; mt < 2; mt++)
#pragma unroll
        for (int nt = 0; nt < 8; nt++)
#pragma unroll
            for (int i = 0; i < 4; i++) c[mt][nt][i] = 0.f;

    for (int k0 = 0; k0 < DMODEL; k0 += 32) {
        float4 xa[4], xb[4];
#pragma unroll
        for (int i = 0; i < 4; i++) {
            const int idx = tid + i * 256;
            const int ar = idx >> 3, ac4 = idx & 7;
            xa[i] = *(const float4*)&X[(size_t)(bm + ar) * DMODEL + k0 + ac4 * 4];
            const int bk = idx >> 5, bc4 = idx & 31;
            xb[i] = *(const float4*)&W[(size_t)(k0 + bk) * HDIM + bn + bc4 * 4];
        }
        __syncthreads();   // previous iter's smem reads complete
#pragma unroll
        for (int i = 0; i < 4; i++) {
            const int idx = tid + i * 256;
            const int ar = idx >> 3, ac4 = idx & 7;
            uint32_t* pa = &As[ar * GLDA + ac4 * 4];
            pa[0] = f2tf(xa[i].x); pa[1] = f2tf(xa[i].y);
            pa[2] = f2tf(xa[i].z); pa[3] = f2tf(xa[i].w);
            const int bk = idx >> 5, bc4 = idx & 31;
            uint32_t* pb = &Bs[bk * GLDB + bc4 * 4];
            pb[0] = f2tf(xb[i].x); pb[1] = f2tf(xb[i].y);
            pb[2] = f2tf(xb[i].z); pb[3] = f2tf(xb[i].w);
        }
        __syncthreads();

#pragma unroll
        for (int ks = 0; ks < 4; ks++) {
            uint32_t a[2][4], b[8][2];
#pragma unroll
            for (int mt = 0; mt < 2; mt++) {
                const int row = wm * 32 + mt * 16 + g;
                a[mt][0] = As[row * GLDA + ks * 8 + t];
                a[mt][1] = As[(row + 8) * GLDA + ks * 8 + t];
                a[mt][2] = As[row * GLDA + ks * 8 + t + 4];
                a[mt][3] = As[(row + 8) * GLDA + ks * 8 + t + 4];
            }
#pragma unroll
            for (int nt = 0; nt < 8; nt++) {
                const int col = wn * 64 + nt * 8 + g;
                b[nt][0] = Bs[(ks * 8 + t) * GLDB + col];
                b[nt][1] = Bs[(ks * 8 + t + 4) * GLDB + col];
            }
#pragma unroll
            for (int mt = 0; mt < 2; mt++)
#pragma unroll
                for (int nt = 0; nt < 8; nt++)
                    mma8(c[mt][nt], a[mt], b[nt][0], b[nt][1]);
        }
    }

    // epilogue
#pragma unroll
    for (int mt = 0; mt < 2; mt++) {
#pragma unroll
        for (int nt = 0; nt < 8; nt++) {
            const int row = bm + wm * 32 + mt * 16 + g;
            const int col = bn + wn * 64 + nt * 8 + t * 2;
            const float b0 = bias[col], b1 = bias[col + 1];
            float2 v0 = make_float2(c[mt][nt][0] + b0, c[mt][nt][1] + b1);
            float2 v1 = make_float2(c[mt][nt][2] + b0, c[mt][nt][3] + b1);
            if (!headsplit) {
                *(float2*)&C[(size_t)row * HDIM + col] = v0;
                *(float2*)&C[(size_t)(row + 8) * HDIM + col] = v1;
            } else {
                const int h = col >> 6, d = col & 63;
                const int n0 = row >> 11, t0 = row & 2047;
                const int n1 = (row + 8) >> 11, t1 = (row + 8) & 2047;
                *(float2*)&C[(size_t)(((n0 * NHEAD + h) * T_SEQ) + t0) * DK + d] = v0;
                *(float2*)&C[(size_t)(((n1 * NHEAD + h) * T_SEQ) + t1) * DK + d] = v1;
            }
        }
    }
}

// ---------------------------------------------------------------------------
// Flash attention, tf32 MMA. Per (n,h): S = (0.125*Q)·V^T + maskbias,
// online softmax, O = P·V. 128 queries/block, 64-key chunks, 8 warps
// (each warp owns 16 full rows -> softmax entirely warp-local).
// ---------------------------------------------------------------------------
#define ALD 68
#define ATTN_SMEM_BYTES ((64 * ALD + 64 * ALD + 128 * ALD) * 4 + T_SEQ * 4)

__global__ __launch_bounds__(256)
void attn_tf32(const float* __restrict__ Q, const float* __restrict__ V,
               const int* __restrict__ mask, float* __restrict__ A)
{
    extern __shared__ uint32_t sm[];
    uint32_t* Vs = sm;                      // [j][d] natural
    uint32_t* Vt = Vs + 64 * ALD;           // [d][j] transposed
    uint32_t* Ps = Vt + 64 * ALD;           // [row][j]
    float* Ms = (float*)(Ps + 128 * ALD);   // additive mask bias [T_SEQ]

    const int tid = threadIdx.x;
    const int lane = tid & 31;
    const int warp = tid >> 5;
    const int g = lane >> 2;
    const int t = lane & 3;
    const int nh = blockIdx.y;
    const int n = nh >> 4;
    const int h = nh & 15;
    const int q0 = blockIdx.x * 128;

    // mask row -> additive bias in smem
#pragma unroll
    for (int i = 0; i < 8; i++) {
        const int j = tid + i * 256;
        Ms[j] = mask[n * T_SEQ + j] ? 0.f : -1e30f;
    }

    // Q fragments in registers for whole kernel, pre-scaled by 1/sqrt(64)
    const float* Qp = Q + ((size_t)nh * T_SEQ + q0 + warp * 16) * DK;
    uint32_t qa[8][4];
#pragma unroll
    for (int kd = 0; kd < 8; kd++) {
        qa[kd][0] = f2tf(0.125f * Qp[g * DK + kd * 8 + t]);
        qa[kd][1] = f2tf(0.125f * Qp[(g + 8) * DK + kd * 8 + t]);
        qa[kd][2] = f2tf(0.125f * Qp[g * DK + kd * 8 + t + 4]);
        qa[kd][3] = f2tf(0.125f * Qp[(g + 8) * DK + kd * 8 + t + 4]);
    }

    float o[8][4];
#pragma unroll
    for (int dt = 0; dt < 8; dt++)
#pragma unroll
        for (int i = 0; i < 4; i++) o[dt][i] = 0.f;
    float m0 = -1e30f, m1 = -1e30f, l0 = 0.f, l1 = 0.f;

    const float* Vp = V + (size_t)nh * T_SEQ * DK;

    for (int j0 = 0; j0 < T_SEQ; j0 += 64) {
        __syncthreads();   // previous chunk's Vs/Vt/Ps reads done (also covers Ms init)

        // V chunk -> Vs (coalesced gmem, mild STS conflict)
#pragma unroll
        for (int i = 0; i < 4; i++) {
            const int idx = tid + i * 256;
            const int j = idx >> 4, d4 = idx & 15;
            float4 v = *(const float4*)&Vp[(size_t)(j0 + j) * DK + d4 * 4];
            uint32_t* p = &Vs[j * ALD + d4 * 4];
            p[0] = f2tf(v.x); p[1] = f2tf(v.y); p[2] = f2tf(v.z); p[3] = f2tf(v.w);
        }
        // V chunk -> Vt transposed (L1-hot gmem reload, conflict-free STS)
#pragma unroll
        for (int i = 0; i < 4; i++) {
            const int idx = tid + i * 256;
            const int j = idx & 63, d4 = idx >> 6;
            float4 v = *(const float4*)&Vp[(size_t)(j0 + j) * DK + d4 * 4];
            Vt[(d4 * 4 + 0) * ALD + j] = f2tf(v.x);
            Vt[(d4 * 4 + 1) * ALD + j] = f2tf(v.y);
            Vt[(d4 * 4 + 2) * ALD + j] = f2tf(v.z);
            Vt[(d4 * 4 + 3) * ALD + j] = f2tf(v.w);
        }
        __syncthreads();

        // S = Qf · V^T  (A = Q frags in regs, B from Vs)
        float s[8][4];
#pragma unroll
        for (int jt = 0; jt < 8; jt++)
#pragma unroll
            for (int i = 0; i < 4; i++) s[jt][i] = 0.f;
#pragma unroll
        for (int kd = 0; kd < 8; kd++) {
            uint32_t b[8][2];
#pragma unroll
            for (int jt = 0; jt < 8; jt++) {
                b[jt][0] = Vs[(jt * 8 + g) * ALD + kd * 8 + t];
                b[jt][1] = Vs[(jt * 8 + g) * ALD + kd * 8 + t + 4];
            }
#pragma unroll
            for (int jt = 0; jt < 8; jt++)
                mma8(s[jt], qa[kd], b[jt][0], b[jt][1]);
        }

        // mask bias
#pragma unroll
        for (int jt = 0; jt < 8; jt++) {
            const float mb0 = Ms[j0 + jt * 8 + t * 2];
            const float mb1 = Ms[j0 + jt * 8 + t * 2 + 1];
            s[jt][0] += mb0; s[jt][1] += mb1;
            s[jt][2] += mb0; s[jt][3] += mb1;
        }

        // online softmax (rows warp*16+g and +8; 4-lane shfl reductions)
        float cm0 = -1e30f, cm1 = -1e30f;
#pragma unroll
        for (int jt = 0; jt < 8; jt++) {
            cm0 = fmaxf(cm0, fmaxf(s[jt][0], s[jt][1]));
            cm1 = fmaxf(cm1, fmaxf(s[jt][2], s[jt][3]));
        }
        cm0 = fmaxf(cm0, __shfl_xor_sync(0xffffffffu, cm0, 1));
        cm0 = fmaxf(cm0, __shfl_xor_sync(0xffffffffu, cm0, 2));
        cm1 = fmaxf(cm1, __shfl_xor_sync(0xffffffffu, cm1, 1));
        cm1 = fmaxf(cm1, __shfl_xor_sync(0xffffffffu, cm1, 2));
        const float nm0 = fmaxf(m0, cm0), nm1 = fmaxf(m1, cm1);
        const float sc0 = __expf(m0 - nm0), sc1 = __expf(m1 - nm1);
        m0 = nm0; m1 = nm1;

        float sum0 = 0.f, sum1 = 0.f;
        const int prow0 = (warp * 16 + g) * ALD;
        const int prow1 = (warp * 16 + g + 8) * ALD;
#pragma unroll
        for (int jt = 0; jt < 8; jt++) {
            const float p0 = __expf(s[jt][0] - nm0);
            const float p1 = __expf(s[jt][1] - nm0);
            const float p2 = __expf(s[jt][2] - nm1);
            const float p3 = __expf(s[jt][3] - nm1);
            sum0 += p0 + p1;
            sum1 += p2 + p3;
            uint2 w0 = make_uint2(f2tf(p0), f2tf(p1));
            uint2 w1 = make_uint2(f2tf(p2), f2tf(p3));
            *(uint2*)&Ps[prow0 + jt * 8 + t * 2] = w0;
            *(uint2*)&Ps[prow1 + jt * 8 + t * 2] = w1;
        }
        sum0 += __shfl_xor_sync(0xffffffffu, sum0, 1);
        sum0 += __shfl_xor_sync(0xffffffffu, sum0, 2);
        sum1 += __shfl_xor_sync(0xffffffffu, sum1, 1);
        sum1 += __shfl_xor_sync(0xffffffffu, sum1, 2);
        l0 = l0 * sc0 + sum0;
        l1 = l1 * sc1 + sum1;
#pragma unroll
        for (int dt = 0; dt < 8; dt++) {
            o[dt][0] *= sc0; o[dt][1] *= sc0;
            o[dt][2] *= sc1; o[dt][3] *= sc1;
        }
        __syncthreads();   // Ps (and Vt) visible to all lanes of this warp set

        // O += P · V  (A from Ps, B from Vt)
#pragma unroll
        for (int kj = 0; kj < 8; kj++) {
            uint32_t a[4];
            a[0] = Ps[prow0 + kj * 8 + t];
            a[1] = Ps[prow1 + kj * 8 + t];
            a[2] = Ps[prow0 + kj * 8 + t + 4];
            a[3] = Ps[prow1 + kj * 8 + t + 4];
#pragma unroll
            for (int dt = 0; dt < 8; dt++) {
                const uint32_t b0 = Vt[(dt * 8 + g) * ALD + kj * 8 + t];
                const uint32_t b1 = Vt[(dt * 8 + g) * ALD + kj * 8 + t + 4];
                mma8(o[dt], a, b0, b1);
            }
        }
    }

    // epilogue: /l, write merged [n, t, h*64+d]
    const float il0 = 1.f / l0, il1 = 1.f / l1;
    const int t0 = q0 + warp * 16 + g;
    const int t1 = t0 + 8;
#pragma unroll
    for (int dt = 0; dt < 8; dt++) {
        const int d = dt * 8 + t * 2;
        float2 v0 = make_float2(o[dt][0] * il0, o[dt][1] * il0);
        float2 v1 = make_float2(o[dt][2] * il1, o[dt][3] * il1);
        *(float2*)&A[(size_t)((n * T_SEQ + t0) * NHEAD + h) * DK + d] = v0;
        *(float2*)&A[(size_t)((n * T_SEQ + t1) * NHEAD + h) * DK + d] = v1;
    }
}

// ---------------------------------------------------------------------------
// Inputs: 0 x_k, 1 x_v, 2 x_q, 3 mask, 4 Wk, 5 bk, 6 Wv, 7 bv,
//         8 Wq, 9 bq, 10 Wf, 11 bf.  K projection is dead code in reference.
// ---------------------------------------------------------------------------
extern "C" void kernel_launch(void* const* d_in, const int* in_sizes, int n_in,
                              void* d_out, int out_size)
{
    const float* x_v  = (const float*)d_in[1];
    const float* x_q  = (const float*)d_in[2];
    const int*   mask = (const int*)d_in[3];
    const float* Wv   = (const float*)d_in[6];
    const float* bv   = (const float*)d_in[7];
    const float* Wq   = (const float*)d_in[8];
    const float* bq   = (const float*)d_in[9];
    const float* Wf   = (const float*)d_in[10];
    const float* bf   = (const float*)d_in[11];
    float* out = (float*)d_out;

    float *gQ, *gV, *gA;
    cudaGetSymbolAddress((void**)&gQ, g_Q);
    cudaGetSymbolAddress((void**)&gV, g_V);
    cudaGetSymbolAddress((void**)&gA, g_A);

    cudaFuncSetAttribute(attn_tf32, cudaFuncAttributeMaxDynamicSharedMemorySize,
                         ATTN_SMEM_BYTES);

    dim3 gg(HDIM / 128, (NB * T_SEQ) / 128);
    gemm_tf32<<<gg, 256>>>(x_q, Wq, bq, gQ, 1);
    gemm_tf32<<<gg, 256>>>(x_v, Wv, bv, gV, 1);
    attn_tf32<<<dim3(T_SEQ / 128, NB * NHEAD), 256, ATTN_SMEM_BYTES>>>(gQ, gV, mask, gA);
    gemm_tf32<<<gg, 256>>>(gA, Wf, bf, out, 0);
}

// round 3
// speedup vs baseline: 4.0697x; 1.0452x over previous
#include <cuda_runtime.h>
#include <cstdint>

#define T_SEQ 2048
#define NB    4
#define NHEAD 16
#define DK    64
#define DMODEL 1024
#define HDIM  1024

// Scratch (allocation-free rule: __device__ globals)
__device__ float g_Q[NB * NHEAD * T_SEQ * DK];     // [n,h,t,d] tf32-rounded
__device__ float g_V[NB * NHEAD * T_SEQ * DK];     // [n,h,t,d] tf32-rounded
__device__ float g_A[NB * T_SEQ * HDIM];           // [n,t,h*d] tf32-rounded
__device__ float g_Xq[NB * T_SEQ * DMODEL];        // tf32-rounded copies
__device__ float g_Xv[NB * T_SEQ * DMODEL];
__device__ float g_Wq[DMODEL * HDIM];
__device__ float g_Wv[DMODEL * HDIM];
__device__ float g_Wf[HDIM * DMODEL];

// ---------------------------------------------------------------------------
// helpers
// ---------------------------------------------------------------------------
__device__ __forceinline__ uint32_t f2tf(float f) {
    uint32_t r;
    asm("cvt.rna.tf32.f32 %0, %1;" : "=r"(r) : "f"(f));
    return r;
}
__device__ __forceinline__ float f2tff(float f) { return __uint_as_float(f2tf(f)); }

__device__ __forceinline__ void mma8(float* c, const uint32_t* a, uint32_t b0, uint32_t b1) {
    asm volatile(
        "mma.sync.aligned.m16n8k8.row.col.f32.tf32.tf32.f32 "
        "{%0,%1,%2,%3}, {%4,%5,%6,%7}, {%8,%9}, {%0,%1,%2,%3};"
        : "+f"(c[0]), "+f"(c[1]), "+f"(c[2]), "+f"(c[3])
        : "r"(a[0]), "r"(a[1]), "r"(a[2]), "r"(a[3]), "r"(b0), "r"(b1));
}

__device__ __forceinline__ void cpa16(uint32_t s, const void* g) {
    asm volatile("cp.async.cg.shared.global [%0], [%1], 16;" :: "r"(s), "l"(g));
}
__device__ __forceinline__ void cpa_commit() {
    asm volatile("cp.async.commit_group;" ::: "memory");
}
template <int N>
__device__ __forceinline__ void cpa_wait() {
    asm volatile("cp.async.wait_group %0;" :: "n"(N) : "memory");
}

// ---------------------------------------------------------------------------
// pre-round fp32 -> tf32-in-fp32 (removes all cvts from GEMM hot loops)
// ---------------------------------------------------------------------------
__global__ void preround(const float4* __restrict__ in, float4* __restrict__ out, int n4) {
    int i = blockIdx.x * blockDim.x + threadIdx.x;
    if (i < n4) {
        float4 v = in[i];
        v.x = f2tff(v.x); v.y = f2tff(v.y); v.z = f2tff(v.z); v.w = f2tff(v.w);
        out[i] = v;
    }
}

// ---------------------------------------------------------------------------
// tf32 GEMM with bias, cp.async 3-stage: C = X[M,1024] @ W[1024,1024] + b
// Inputs pre-rounded to tf32. Block 128x128, k-step 16, 8 warps (4m x 2n).
// headsplit=1: round + scatter to [n,h,t,d].
// ---------------------------------------------------------------------------
#define AST 20    // As row stride (words): 16 k + 4 pad
#define BST 136   // Bs row stride (words): 128 n + 8 pad
#define NSTG 3
#define GEMM_SMEM ((128 * AST + 16 * BST) * 4 * NSTG)   // 56832 B

__global__ __launch_bounds__(256, 2)
void gemm_tf32(const float* __restrict__ X, const float* __restrict__ W,
               const float* __restrict__ bias, float* __restrict__ C, int headsplit)
{
    extern __shared__ uint32_t sm[];
    uint32_t* As = sm;                         // [NSTG][128][AST]
    uint32_t* Bs = sm + NSTG * 128 * AST;      // [NSTG][16][BST]

    const int tid = threadIdx.x;
    const int lane = tid & 31;
    const int warp = tid >> 5;
    const int g = lane >> 2;
    const int t = lane & 3;
    const int wm = warp & 3;
    const int wn = warp >> 2;
    const int bm = blockIdx.y * 128;
    const int bn = blockIdx.x * 128;

    const uint32_t sA = (uint32_t)__cvta_generic_to_shared(As);
    const uint32_t sB = (uint32_t)__cvta_generic_to_shared(Bs);

    // copy coords (2 A-chunks + 2 B-chunks of 16B per thread per stage)
    const int a_r0 = tid >> 2, a_kg = (tid & 3) * 4;           // rows 0..63
    const int b_k0 = tid >> 5, b_ng = (tid & 31) * 4;          // krows 0..7

    float c[2][8][4];
#pragma unroll
    for (int mt = 0; mt < 2; mt++)
#pragma unroll
        for (int nt = 0; nt < 8; nt++)
#pragma unroll
            for (int i = 0; i < 4; i++) c[mt][nt][i] = 0.f;

#define ISSUE(stage, kk)                                                          \
    do {                                                                          \
        const uint32_t abase = sA + (uint32_t)(stage) * 128 * AST * 4;            \
        const uint32_t bbase = sB + (uint32_t)(stage) * 16 * BST * 4;             \
        cpa16(abase + (uint32_t)(a_r0 * AST + a_kg) * 4,                          \
              &X[(size_t)(bm + a_r0) * DMODEL + (kk) + a_kg]);                    \
        cpa16(abase + (uint32_t)((a_r0 + 64) * AST + a_kg) * 4,                   \
              &X[(size_t)(bm + a_r0 + 64) * DMODEL + (kk) + a_kg]);               \
        cpa16(bbase + (uint32_t)(b_k0 * BST + b_ng) * 4,                          \
              &W[(size_t)((kk) + b_k0) * HDIM + bn + b_ng]);                      \
        cpa16(bbase + (uint32_t)((b_k0 + 8) * BST + b_ng) * 4,                    \
              &W[(size_t)((kk) + b_k0 + 8) * HDIM + bn + b_ng]);                  \
    } while (0)

    ISSUE(0, 0);  cpa_commit();
    ISSUE(1, 16); cpa_commit();
    cpa_wait<1>();
    __syncthreads();

    const int NKT = DMODEL / 16;   // 64
    for (int kt = 0; kt < NKT; kt++) {
        const int cur = kt % NSTG;
        if (kt + 2 < NKT) ISSUE((kt + 2) % NSTG, (kt + 2) * 16);
        cpa_commit();   // empty group near tail keeps bookkeeping uniform

        const uint32_t* Ac = As + cur * 128 * AST;
        const uint32_t* Bc = Bs + cur * 16 * BST;
#pragma unroll
        for (int ks = 0; ks < 2; ks++) {
            uint32_t a[2][4];
#pragma unroll
            for (int mt = 0; mt < 2; mt++) {
                const int row = wm * 32 + mt * 16 + g;
                a[mt][0] = Ac[row * AST + ks * 8 + t];
                a[mt][1] = Ac[(row + 8) * AST + ks * 8 + t];
                a[mt][2] = Ac[row * AST + ks * 8 + t + 4];
                a[mt][3] = Ac[(row + 8) * AST + ks * 8 + t + 4];
            }
#pragma unroll
            for (int nt = 0; nt < 8; nt++) {
                const int col = wn * 64 + nt * 8 + g;
                const uint32_t b0 = Bc[(ks * 8 + t) * BST + col];
                const uint32_t b1 = Bc[(ks * 8 + t + 4) * BST + col];
                mma8(c[0][nt], a[0], b0, b1);
                mma8(c[1][nt], a[1], b0, b1);
            }
        }
        cpa_wait<1>();
        __syncthreads();
    }
#undef ISSUE

    // epilogue
#pragma unroll
    for (int mt = 0; mt < 2; mt++) {
#pragma unroll
        for (int nt = 0; nt < 8; nt++) {
            const int row = bm + wm * 32 + mt * 16 + g;
            const int col = bn + wn * 64 + nt * 8 + t * 2;
            const float b0 = bias[col], b1 = bias[col + 1];
            float2 v0 = make_float2(c[mt][nt][0] + b0, c[mt][nt][1] + b1);
            float2 v1 = make_float2(c[mt][nt][2] + b0, c[mt][nt][3] + b1);
            if (!headsplit) {
                *(float2*)&C[(size_t)row * HDIM + col] = v0;
                *(float2*)&C[(size_t)(row + 8) * HDIM + col] = v1;
            } else {
                v0.x = f2tff(v0.x); v0.y = f2tff(v0.y);
                v1.x = f2tff(v1.x); v1.y = f2tff(v1.y);
                const int h = col >> 6, d = col & 63;
                const int n0 = row >> 11, t0 = row & 2047;
                const int n1 = (row + 8) >> 11, t1 = (row + 8) & 2047;
                *(float2*)&C[(size_t)(((n0 * NHEAD + h) * T_SEQ) + t0) * DK + d] = v0;
                *(float2*)&C[(size_t)(((n1 * NHEAD + h) * T_SEQ) + t1) * DK + d] = v1;
            }
        }
    }
}

// ---------------------------------------------------------------------------
// Flash attention, tf32 MMA, base-2 softmax. Q pre-scaled by 0.125*log2e and
// held in registers. V pre-rounded -> pure bit copies. 2 CTAs/SM.
// ---------------------------------------------------------------------------
#define ALD 68
#define ATTN_SMEM ((64 * ALD + 64 * ALD + 128 * ALD) * 4 + T_SEQ * 4)

__global__ __launch_bounds__(256, 2)
void attn_tf32(const float* __restrict__ Q, const float* __restrict__ V,
               const int* __restrict__ mask, float* __restrict__ A)
{
    extern __shared__ uint32_t sm[];
    uint32_t* Vs = sm;                      // [j][d]
    uint32_t* Vt = Vs + 64 * ALD;           // [d][j]
    uint32_t* Ps = Vt + 64 * ALD;           // [row][j]
    float* Ms = (float*)(Ps + 128 * ALD);   // mask bias [T_SEQ]

    const int tid = threadIdx.x;
    const int lane = tid & 31;
    const int warp = tid >> 5;
    const int g = lane >> 2;
    const int t = lane & 3;
    const int nh = blockIdx.y;
    const int n = nh >> 4;
    const int h = nh & 15;
    const int q0 = blockIdx.x * 128;

    const uint32_t sVs = (uint32_t)__cvta_generic_to_shared(Vs);

#pragma unroll
    for (int i = 0; i < 8; i++) {
        const int j = tid + i * 256;
        Ms[j] = mask[n * T_SEQ + j] ? 0.f : -1e30f;
    }

    // Q fragments in registers, pre-scaled by 0.125*log2(e)
    const float QSC = 0.18033688f;
    const float* Qp = Q + ((size_t)nh * T_SEQ + q0 + warp * 16) * DK;
    uint32_t qa[8][4];
#pragma unroll
    for (int kd = 0; kd < 8; kd++) {
        qa[kd][0] = f2tf(QSC * Qp[g * DK + kd * 8 + t]);
        qa[kd][1] = f2tf(QSC * Qp[(g + 8) * DK + kd * 8 + t]);
        qa[kd][2] = f2tf(QSC * Qp[g * DK + kd * 8 + t + 4]);
        qa[kd][3] = f2tf(QSC * Qp[(g + 8) * DK + kd * 8 + t + 4]);
    }

    float o[8][4];
#pragma unroll
    for (int dt = 0; dt < 8; dt++)
#pragma unroll
        for (int i = 0; i < 4; i++) o[dt][i] = 0.f;
    float m0 = -1e30f, m1 = -1e30f, l0 = 0.f, l1 = 0.f;

    const float* Vp = V + (size_t)nh * T_SEQ * DK;

    for (int j0 = 0; j0 < T_SEQ; j0 += 64) {
        __syncthreads();   // prev chunk's Vs/Vt/Ps reads done

        // Vs natural via cp.async (values already tf32-rounded)
#pragma unroll
        for (int i = 0; i < 4; i++) {
            const int idx = tid + i * 256;
            const int j = idx >> 4, d4 = (idx & 15) * 4;
            cpa16(sVs + (uint32_t)(j * ALD + d4) * 4, &Vp[(size_t)(j0 + j) * DK + d4]);
        }
        cpa_commit();
        // Vt transposed via LDG (L1/L2-hot reload) + STS
#pragma unroll
        for (int i = 0; i < 4; i++) {
            const int idx = tid + i * 256;
            const int j = idx & 63, d4 = idx >> 6;
            float4 v = *(const float4*)&Vp[(size_t)(j0 + j) * DK + d4 * 4];
            Vt[(d4 * 4 + 0) * ALD + j] = __float_as_uint(v.x);
            Vt[(d4 * 4 + 1) * ALD + j] = __float_as_uint(v.y);
            Vt[(d4 * 4 + 2) * ALD + j] = __float_as_uint(v.z);
            Vt[(d4 * 4 + 3) * ALD + j] = __float_as_uint(v.w);
        }
        cpa_wait<0>();
        __syncthreads();

        // S = Qf · V^T
        float s[8][4];
#pragma unroll
        for (int jt = 0; jt < 8; jt++)
#pragma unroll
            for (int i = 0; i < 4; i++) s[jt][i] = 0.f;
#pragma unroll
        for (int kd = 0; kd < 8; kd++) {
#pragma unroll
            for (int jt = 0; jt < 8; jt++) {
                const uint32_t b0 = Vs[(jt * 8 + g) * ALD + kd * 8 + t];
                const uint32_t b1 = Vs[(jt * 8 + g) * ALD + kd * 8 + t + 4];
                mma8(s[jt], qa[kd], b0, b1);
            }
        }

        // mask bias
#pragma unroll
        for (int jt = 0; jt < 8; jt++) {
            const float mb0 = Ms[j0 + jt * 8 + t * 2];
            const float mb1 = Ms[j0 + jt * 8 + t * 2 + 1];
            s[jt][0] += mb0; s[jt][1] += mb1;
            s[jt][2] += mb0; s[jt][3] += mb1;
        }

        // online softmax in base-2 (4-lane shfl reductions)
        float cm0 = -1e30f, cm1 = -1e30f;
#pragma unroll
        for (int jt = 0; jt < 8; jt++) {
            cm0 = fmaxf(cm0, fmaxf(s[jt][0], s[jt][1]));
            cm1 = fmaxf(cm1, fmaxf(s[jt][2], s[jt][3]));
        }
        cm0 = fmaxf(cm0, __shfl_xor_sync(0xffffffffu, cm0, 1));
        cm0 = fmaxf(cm0, __shfl_xor_sync(0xffffffffu, cm0, 2));
        cm1 = fmaxf(cm1, __shfl_xor_sync(0xffffffffu, cm1, 1));
        cm1 = fmaxf(cm1, __shfl_xor_sync(0xffffffffu, cm1, 2));
        const float nm0 = fmaxf(m0, cm0), nm1 = fmaxf(m1, cm1);
        const float sc0 = exp2f(m0 - nm0), sc1 = exp2f(m1 - nm1);
        m0 = nm0; m1 = nm1;

        float sum0 = 0.f, sum1 = 0.f;
        const int prow0 = (warp * 16 + g) * ALD;
        const int prow1 = (warp * 16 + g + 8) * ALD;
#pragma unroll
        for (int jt = 0; jt < 8; jt++) {
            const float p0 = exp2f(s[jt][0] - nm0);
            const float p1 = exp2f(s[jt][1] - nm0);
            const float p2 = exp2f(s[jt][2] - nm1);
            const float p3 = exp2f(s[jt][3] - nm1);
            sum0 += p0 + p1;
            sum1 += p2 + p3;
            *(uint2*)&Ps[prow0 + jt * 8 + t * 2] = make_uint2(f2tf(p0), f2tf(p1));
            *(uint2*)&Ps[prow1 + jt * 8 + t * 2] = make_uint2(f2tf(p2), f2tf(p3));
        }
        sum0 += __shfl_xor_sync(0xffffffffu, sum0, 1);
        sum0 += __shfl_xor_sync(0xffffffffu, sum0, 2);
        sum1 += __shfl_xor_sync(0xffffffffu, sum1, 1);
        sum1 += __shfl_xor_sync(0xffffffffu, sum1, 2);
        l0 = l0 * sc0 + sum0;
        l1 = l1 * sc1 + sum1;
#pragma unroll
        for (int dt = 0; dt < 8; dt++) {
            o[dt][0] *= sc0; o[dt][1] *= sc0;
            o[dt][2] *= sc1; o[dt][3] *= sc1;
        }
        __syncthreads();

        // O += P · V
#pragma unroll
        for (int kj = 0; kj < 8; kj++) {
            uint32_t a[4];
            a[0] = Ps[prow0 + kj * 8 + t];
            a[1] = Ps[prow1 + kj * 8 + t];
            a[2] = Ps[prow0 + kj * 8 + t + 4];
            a[3] = Ps[prow1 + kj * 8 + t + 4];
#pragma unroll
            for (int dt = 0; dt < 8; dt++) {
                const uint32_t b0 = Vt[(dt * 8 + g) * ALD + kj * 8 + t];
                const uint32_t b1 = Vt[(dt * 8 + g) * ALD + kj * 8 + t + 4];
                mma8(o[dt], a, b0, b1);
            }
        }
    }

    // epilogue: /l, round to tf32 (feeds final GEMM), write [n, t, h*64+d]
    const float il0 = 1.f / l0, il1 = 1.f / l1;
    const int t0 = q0 + warp * 16 + g;
    const int t1 = t0 + 8;
#pragma unroll
    for (int dt = 0; dt < 8; dt++) {
        const int d = dt * 8 + t * 2;
        float2 v0 = make_float2(f2tff(o[dt][0] * il0), f2tff(o[dt][1] * il0));
        float2 v1 = make_float2(f2tff(o[dt][2] * il1), f2tff(o[dt][3] * il1));
        *(float2*)&A[(size_t)((n * T_SEQ + t0) * NHEAD + h) * DK + d] = v0;
        *(float2*)&A[(size_t)((n * T_SEQ + t1) * NHEAD + h) * DK + d] = v1;
    }
}

// ---------------------------------------------------------------------------
// Inputs: 0 x_k, 1 x_v, 2 x_q, 3 mask, 4 Wk, 5 bk, 6 Wv, 7 bv,
//         8 Wq, 9 bq, 10 Wf, 11 bf.  K projection is dead code in reference.
// ---------------------------------------------------------------------------
extern "C" void kernel_launch(void* const* d_in, const int* in_sizes, int n_in,
                              void* d_out, int out_size)
{
    const float* x_v  = (const float*)d_in[1];
    const float* x_q  = (const float*)d_in[2];
    const int*   mask = (const int*)d_in[3];
    const float* Wv   = (const float*)d_in[6];
    const float* bv   = (const float*)d_in[7];
    const float* Wq   = (const float*)d_in[8];
    const float* bq   = (const float*)d_in[9];
    const float* Wf   = (const float*)d_in[10];
    const float* bf   = (const float*)d_in[11];
    float* out = (float*)d_out;

    float *gQ, *gV, *gA, *gXq, *gXv, *gWq, *gWv, *gWf;
    cudaGetSymbolAddress((void**)&gQ, g_Q);
    cudaGetSymbolAddress((void**)&gV, g_V);
    cudaGetSymbolAddress((void**)&gA, g_A);
    cudaGetSymbolAddress((void**)&gXq, g_Xq);
    cudaGetSymbolAddress((void**)&gXv, g_Xv);
    cudaGetSymbolAddress((void**)&gWq, g_Wq);
    cudaGetSymbolAddress((void**)&gWv, g_Wv);
    cudaGetSymbolAddress((void**)&gWf, g_Wf);

    cudaFuncSetAttribute(gemm_tf32, cudaFuncAttributeMaxDynamicSharedMemorySize, GEMM_SMEM);
    cudaFuncSetAttribute(attn_tf32, cudaFuncAttributeMaxDynamicSharedMemorySize, ATTN_SMEM);

    const int nx4 = NB * T_SEQ * DMODEL / 4;   // 2M
    const int nw4 = DMODEL * HDIM / 4;         // 256K
    preround<<<nx4 / 256, 256>>>((const float4*)x_q, (float4*)gXq, nx4);
    preround<<<nx4 / 256, 256>>>((const float4*)x_v, (float4*)gXv, nx4);
    preround<<<nw4 / 256, 256>>>((const float4*)Wq, (float4*)gWq, nw4);
    preround<<<nw4 / 256, 256>>>((const float4*)Wv, (float4*)gWv, nw4);
    preround<<<nw4 / 256, 256>>>((const float4*)Wf, (float4*)gWf, nw4);

    dim3 gg(HDIM / 128, (NB * T_SEQ) / 128);
    gemm_tf32<<<gg, 256, GEMM_SMEM>>>(gXq, gWq, bq, gQ, 1);
    gemm_tf32<<<gg, 256, GEMM_SMEM>>>(gXv, gWv, bv, gV, 1);
    attn_tf32<<<dim3(T_SEQ / 128, NB * NHEAD), 256, ATTN_SMEM>>>(gQ, gV, mask, gA);
    gemm_tf32<<<gg, 256, GEMM_SMEM>>>(gA, gWf, bf, out, 0);
}